// round 6
// baseline (speedup 1.0000x reference)
#include <cuda_runtime.h>
#include <math.h>
#include <stdint.h>

// ---------------- problem constants ----------------
#define B_    4
#define LQ_   512
#define LKV_  8192
#define QDIM  1024
#define KVDIM 512
#define CH    256      // QK_CH == V_CH == 256 (GEMM N)
#define HEADS 8
#define DH    32
#define QSCALE 0.2550348587f   // (1/sqrt(32)) * log2(e)

// ---------------- scratch ----------------
__device__ float g_hsn_hi [B_*LQ_*QDIM];
__device__ float g_hsn_lo [B_*LQ_*QDIM];
__device__ float g_inpn_hi[B_*LKV_*KVDIM];
__device__ float g_inpn_lo[B_*LKV_*KVDIM];
__device__ float g_q  [B_*LQ_*CH];
__device__ float g_k  [B_*LKV_*CH];
__device__ float g_v  [B_*LKV_*CH];
__device__ float g_wqh[QDIM*CH],  g_wql[QDIM*CH];
__device__ float g_wkh[KVDIM*CH], g_wkl[KVDIM*CH];
__device__ float g_wvh[KVDIM*CH], g_wvl[KVDIM*CH];

// ================= helpers (baseline PTX only) =================
__device__ __forceinline__ uint32_t smem_u32(const void* p){
    uint32_t a; asm("{ .reg .u64 t; cvta.to.shared.u64 t, %1; cvt.u32.u64 %0, t; }" : "=r"(a) : "l"(p)); return a;
}
__device__ __forceinline__ uint32_t f2tf32(float f){
    uint32_t t; asm("cvt.rna.tf32.f32 %0, %1;" : "=r"(t) : "f"(f)); return t;
}
__device__ __forceinline__ float fexp2(float x){
    float y; asm("ex2.approx.ftz.f32 %0, %1;" : "=f"(y) : "f"(x)); return y;
}
__device__ __forceinline__ void cpa16(uint32_t dst, const void* src){
    asm volatile("cp.async.ca.shared.global [%0], [%1], 16;" :: "r"(dst), "l"(src) : "memory");
}
#define CPA_COMMIT() asm volatile("cp.async.commit_group;" ::: "memory")
#define CPA_WAIT(n)  asm volatile("cp.async.wait_group " #n ";" ::: "memory")

// m16n8k8 tf32 mma: D = A*B + D (A row-major, B col-major)
__device__ __forceinline__ void mma8(float* c, const uint32_t* a, uint32_t b0, uint32_t b1){
    asm volatile("mma.sync.aligned.m16n8k8.row.col.f32.tf32.tf32.f32 "
        "{%0,%1,%2,%3}, {%4,%5,%6,%7}, {%8,%9}, {%0,%1,%2,%3};"
        : "+f"(c[0]), "+f"(c[1]), "+f"(c[2]), "+f"(c[3])
        : "r"(a[0]), "r"(a[1]), "r"(a[2]), "r"(a[3]), "r"(b0), "r"(b1));
}

// ---------------- LayerNorm with tf32 hi/lo split outputs ----------------
template<int N>
__global__ __launch_bounds__(256) void ln_split_kernel(
    const float* __restrict__ x, const float* __restrict__ g,
    const float* __restrict__ b, float* __restrict__ yhi, float* __restrict__ ylo)
{
    constexpr int T = 256;
    constexpr int PER = N / T;
    const int row = blockIdx.x;
    const float* xr = x + (size_t)row * N;

    float v[PER];
    float s = 0.f, sq = 0.f;
#pragma unroll
    for (int i = 0; i < PER; i++) {
        v[i] = xr[threadIdx.x + i * T];
        s  += v[i];
        sq += v[i] * v[i];
    }
#pragma unroll
    for (int o = 16; o > 0; o >>= 1) {
        s  += __shfl_xor_sync(0xffffffffu, s,  o);
        sq += __shfl_xor_sync(0xffffffffu, sq, o);
    }
    __shared__ float rs[8], rq[8];
    const int warp = threadIdx.x >> 5, lane = threadIdx.x & 31;
    if (lane == 0) { rs[warp] = s; rq[warp] = sq; }
    __syncthreads();
    if (threadIdx.x == 0) {
        float ts = 0.f, tq = 0.f;
#pragma unroll
        for (int i = 0; i < 8; i++) { ts += rs[i]; tq += rq[i]; }
        rs[0] = ts; rq[0] = tq;
    }
    __syncthreads();
    const float mean = rs[0] * (1.f / N);
    const float var  = rq[0] * (1.f / N) - mean * mean;
    const float rstd = rsqrtf(var + 1e-5f);

    float* yh = yhi + (size_t)row * N;
    float* yl = ylo + (size_t)row * N;
#pragma unroll
    for (int i = 0; i < PER; i++) {
        const int c = threadIdx.x + i * T;
        const float y = (v[i] - mean) * rstd * g[c] + b[c];
        const uint32_t hi = f2tf32(y);
        yh[c] = __uint_as_float(hi);
        yl[c] = __uint_as_float(f2tf32(y - __uint_as_float(hi)));
    }
}

// ---------------- weight split (elementwise) ----------------
__global__ void split_w_kernel(const float* __restrict__ w,
                               float* __restrict__ wh, float* __restrict__ wl, int n)
{
    const int i = blockIdx.x * 256 + threadIdx.x;
    if (i < n) {
        const float x = w[i];
        const uint32_t hi = f2tf32(x);
        wh[i] = __uint_as_float(hi);
        wl[i] = __uint_as_float(f2tf32(x - __uint_as_float(hi)));
    }
}

// ---------------- tf32 split-compensated GEMM ----------------
// C[M,256] = (Ah+Al) @ (Wh+Wl) + bias  ~=  Ah·Wh + Al·Wh + Ah·Wl + bias
// CTA 128x128, 8 warps (4x2), warp tile 32x64, k-step 16, cp.async x2 buffers.
#define GBM 128
#define GBN 128
#define GBK 16
#define ALD 20      // A smem leading dim (floats)
#define WLD 136     // W smem leading dim (floats)
#define ASZ (GBM*ALD)
#define WSZ (GBK*WLD)
#define GEMM_SMEM ((4*ASZ + 4*WSZ) * (int)sizeof(float))   // 75776 B

__global__ void __launch_bounds__(256) gemm_tf32_kernel(
    const float* __restrict__ Ah, const float* __restrict__ Al,
    const float* __restrict__ Wh, const float* __restrict__ Wl,
    const float* __restrict__ bias, float* __restrict__ C,
    int M, int K)
{
    extern __shared__ float sm[];
    float* sAh[2] = { sm,             sm + ASZ };
    float* sAl[2] = { sm + 2*ASZ,     sm + 3*ASZ };
    float* sWh[2] = { sm + 4*ASZ,         sm + 4*ASZ + WSZ };
    float* sWl[2] = { sm + 4*ASZ + 2*WSZ, sm + 4*ASZ + 3*WSZ };

    const int tid  = threadIdx.x;
    const int wid  = tid >> 5;
    const int lane = tid & 31;
    const int g    = lane >> 2;
    const int tig  = lane & 3;
    const int bm   = blockIdx.x * GBM;
    const int bn   = blockIdx.y * GBN;
    const int wm   = (wid & 3) * 32;       // warp m offset in CTA tile
    const int wn   = (wid >> 2) * 64;      // warp n offset

#define G_ISSUE(s, nb) do {                                                        \
    const int _k0 = (s) * GBK;                                                     \
    _Pragma("unroll")                                                              \
    for (int i = 0; i < 2; i++) {                                                  \
        const int idx = tid + i * 256;                                             \
        const int ar = idx >> 2, aq4 = (idx & 3) * 4;                              \
        cpa16(smem_u32(&sAh[nb][ar*ALD + aq4]), Ah + (size_t)(bm+ar)*K + _k0 + aq4);\
        cpa16(smem_u32(&sAl[nb][ar*ALD + aq4]), Al + (size_t)(bm+ar)*K + _k0 + aq4);\
        const int wr = idx >> 5, wc = (idx & 31) * 4;                              \
        cpa16(smem_u32(&sWh[nb][wr*WLD + wc]), Wh + (size_t)(_k0+wr)*CH + bn + wc); \
        cpa16(smem_u32(&sWl[nb][wr*WLD + wc]), Wl + (size_t)(_k0+wr)*CH + bn + wc); \
    }                                                                              \
    CPA_COMMIT();                                                                  \
} while (0)

    float cacc[2][8][4];
#pragma unroll
    for (int i = 0; i < 2; i++)
#pragma unroll
        for (int n = 0; n < 8; n++)
#pragma unroll
            for (int r = 0; r < 4; r++) cacc[i][n][r] = 0.f;

    const int NS = K / GBK;
    G_ISSUE(0, 0);

    for (int s = 0; s < NS; s++) {
        const int nb = s & 1;
        if (s < NS - 1) { G_ISSUE(s + 1, (s + 1) & 1); CPA_WAIT(1); }
        else            { CPA_WAIT(0); }
        __syncthreads();

        const uint32_t* uAh = (const uint32_t*)sAh[nb];
        const uint32_t* uAl = (const uint32_t*)sAl[nb];
        const uint32_t* uWh = (const uint32_t*)sWh[nb];
        const uint32_t* uWl = (const uint32_t*)sWl[nb];

#pragma unroll
        for (int k8 = 0; k8 < 2; k8++) {
            const int kc = k8 * 8 + tig;
            uint32_t ah[2][4], al[2][4];
#pragma unroll
            for (int i = 0; i < 2; i++) {
                const int r0 = (wm + i * 16 + g) * ALD;
                const int r1 = (wm + i * 16 + g + 8) * ALD;
                ah[i][0] = uAh[r0 + kc];  ah[i][1] = uAh[r1 + kc];
                ah[i][2] = uAh[r0 + kc + 4]; ah[i][3] = uAh[r1 + kc + 4];
                al[i][0] = uAl[r0 + kc];  al[i][1] = uAl[r1 + kc];
                al[i][2] = uAl[r0 + kc + 4]; al[i][3] = uAl[r1 + kc + 4];
            }
#pragma unroll
            for (int ng = 0; ng < 2; ng++) {
                uint32_t bh[4][2], bl[4][2];
#pragma unroll
                for (int nf = 0; nf < 4; nf++) {
                    const int n = wn + (ng * 4 + nf) * 8 + g;
                    const int rk0 = (k8 * 8 + tig) * WLD + n;
                    const int rk1 = (k8 * 8 + tig + 4) * WLD + n;
                    bh[nf][0] = uWh[rk0]; bh[nf][1] = uWh[rk1];
                    bl[nf][0] = uWl[rk0]; bl[nf][1] = uWl[rk1];
                }
#pragma unroll
                for (int nf = 0; nf < 4; nf++) {
                    const int n = ng * 4 + nf;
                    mma8(cacc[0][n], ah[0], bh[nf][0], bh[nf][1]);
                    mma8(cacc[1][n], ah[1], bh[nf][0], bh[nf][1]);
                    mma8(cacc[0][n], al[0], bh[nf][0], bh[nf][1]);
                    mma8(cacc[1][n], al[1], bh[nf][0], bh[nf][1]);
                    mma8(cacc[0][n], ah[0], bl[nf][0], bl[nf][1]);
                    mma8(cacc[1][n], ah[1], bl[nf][0], bl[nf][1]);
                }
            }
        }
        __syncthreads();
    }

    // ---- epilogue: bias + store ----
#pragma unroll
    for (int i = 0; i < 2; i++) {
#pragma unroll
        for (int n = 0; n < 8; n++) {
            const int col = bn + wn + n * 8 + 2 * tig;
            const float b0 = bias[col], b1 = bias[col + 1];
            const int r0 = bm + wm + i * 16 + g;
            float2 w0 = make_float2(cacc[i][n][0] + b0, cacc[i][n][1] + b1);
            float2 w1 = make_float2(cacc[i][n][2] + b0, cacc[i][n][3] + b1);
            *(float2*)(C + (size_t)r0 * CH + col)       = w0;
            *(float2*)(C + (size_t)(r0 + 8) * CH + col) = w1;
        }
    }
}

// ================= mma.sync tf32 flash attention (unchanged, passing) ========
#define BQ    64
#define BKV   64
#define NT    (LKV_ / BKV)   // 128
#define LDK   36

__global__ void __launch_bounds__(128) attn_mma_kernel(
    const float* __restrict__ Q, const float* __restrict__ K,
    const float* __restrict__ V, float* __restrict__ O)
{
    __shared__ float Ks[2][BKV][LDK];
    __shared__ float Vs[2][BKV][LDK];

    const int tid  = threadIdx.x;
    const int wid  = tid >> 5;
    const int lane = tid & 31;
    const int g    = lane >> 2;
    const int tig  = lane & 3;
    const int q0   = blockIdx.x * BQ;
    const int h    = blockIdx.y;
    const int b    = blockIdx.z;
    const int qw   = q0 + wid * 16;

    const float* Qb = Q + ((size_t)(b * LQ_ + qw)) * CH + h * DH;
    const float* Kb = K + ((size_t)b * LKV_) * CH + h * DH;
    const float* Vb = V + ((size_t)b * LKV_) * CH + h * DH;

    uint32_t aq[4][4];
#pragma unroll
    for (int kc = 0; kc < 4; kc++) {
        const int c0 = kc * 8 + tig;
        aq[kc][0] = f2tf32(Qb[(size_t)g       * CH + c0    ] * QSCALE);
        aq[kc][1] = f2tf32(Qb[(size_t)(g + 8) * CH + c0    ] * QSCALE);
        aq[kc][2] = f2tf32(Qb[(size_t)g       * CH + c0 + 4] * QSCALE);
        aq[kc][3] = f2tf32(Qb[(size_t)(g + 8) * CH + c0 + 4] * QSCALE);
    }

    float oacc[4][4];
#pragma unroll
    for (int i = 0; i < 4; i++)
#pragma unroll
        for (int r = 0; r < 4; r++) oacc[i][r] = 0.f;
    float lrow[2] = {0.f, 0.f};

    const int prow = tid >> 3;
    const int pc   = (tid & 7) * 4;
#define ISSUE_TILE(j, nb) do {                                                     \
    const int _k0 = (j) * BKV;                                                     \
    _Pragma("unroll")                                                              \
    for (int t = 0; t < 4; t++) {                                                  \
        const int rw = prow + t * 16;                                              \
        cpa16(smem_u32(&Ks[nb][rw][pc]), Kb + (size_t)(_k0 + rw) * CH + pc);       \
        cpa16(smem_u32(&Vs[nb][rw][pc]), Vb + (size_t)(_k0 + rw) * CH + pc);       \
    }                                                                              \
    CPA_COMMIT();                                                                  \
} while (0)

    ISSUE_TILE(0, 0);

    for (int j = 0; j < NT; j++) {
        const int nb = j & 1;
        if (j < NT - 1) { ISSUE_TILE(j + 1, (j + 1) & 1); CPA_WAIT(1); }
        else            { CPA_WAIT(0); }
        __syncthreads();

        float sacc[8][4];
#pragma unroll
        for (int n = 0; n < 8; n++)
#pragma unroll
            for (int r = 0; r < 4; r++) sacc[n][r] = 0.f;

#pragma unroll
        for (int nch = 0; nch < 8; nch++) {
            const float* krow = &Ks[nb][nch * 8 + g][0];
#pragma unroll
            for (int kc = 0; kc < 4; kc++) {
                const uint32_t b0 = __float_as_uint(krow[kc * 8 + tig]);
                const uint32_t b1 = __float_as_uint(krow[kc * 8 + tig + 4]);
                mma8(sacc[nch], aq[kc], b0, b1);
            }
        }

#pragma unroll
        for (int n = 0; n < 8; n++) {
#pragma unroll
            for (int r = 0; r < 4; r++) {
                const float p = fexp2(sacc[n][r]);
                sacc[n][r] = p;
                lrow[r >> 1] += p;
            }
        }

#pragma unroll
        for (int kc = 0; kc < 8; kc++) {
            const int src0 = (lane & ~3) | (tig >> 1);
            const int src2 = src0 + 2;
            const float v00 = __shfl_sync(0xffffffffu, sacc[kc][0], src0);
            const float v01 = __shfl_sync(0xffffffffu, sacc[kc][1], src0);
            const float v10 = __shfl_sync(0xffffffffu, sacc[kc][2], src0);
            const float v11 = __shfl_sync(0xffffffffu, sacc[kc][3], src0);
            const float v20 = __shfl_sync(0xffffffffu, sacc[kc][0], src2);
            const float v21 = __shfl_sync(0xffffffffu, sacc[kc][1], src2);
            const float v30 = __shfl_sync(0xffffffffu, sacc[kc][2], src2);
            const float v31 = __shfl_sync(0xffffffffu, sacc[kc][3], src2);
            uint32_t ap[4];
            const bool odd = (tig & 1);
            ap[0] = f2tf32(odd ? v01 : v00);
            ap[1] = f2tf32(odd ? v11 : v10);
            ap[2] = f2tf32(odd ? v21 : v20);
            ap[3] = f2tf32(odd ? v31 : v30);

            const float* vr0 = &Vs[nb][kc * 8 + tig][0];
            const float* vr1 = &Vs[nb][kc * 8 + tig + 4][0];
#pragma unroll
            for (int nch = 0; nch < 4; nch++) {
                const uint32_t b0 = __float_as_uint(vr0[nch * 8 + g]);
                const uint32_t b1 = __float_as_uint(vr1[nch * 8 + g]);
                mma8(oacc[nch], ap, b0, b1);
            }
        }
        __syncthreads();
    }

#pragma unroll
    for (int r = 0; r < 2; r++) {
        lrow[r] += __shfl_xor_sync(0xffffffffu, lrow[r], 1);
        lrow[r] += __shfl_xor_sync(0xffffffffu, lrow[r], 2);
    }
    const float inv0 = 1.f / lrow[0];
    const float inv1 = 1.f / lrow[1];

    float* Ob = O + ((size_t)(b * LQ_ + qw)) * CH + h * DH;
#pragma unroll
    for (int nch = 0; nch < 4; nch++) {
        const int c = nch * 8 + 2 * tig;
        float2 w0 = make_float2(oacc[nch][0] * inv0, oacc[nch][1] * inv0);
        float2 w1 = make_float2(oacc[nch][2] * inv1, oacc[nch][3] * inv1);
        *(float2*)(Ob + (size_t)g       * CH + c) = w0;
        *(float2*)(Ob + (size_t)(g + 8) * CH + c) = w1;
    }
}

// ---------------- launch ----------------
extern "C" void kernel_launch(void* const* d_in, const int* in_sizes, int n_in,
                              void* d_out, int out_size)
{
    const float* hidden = (const float*)d_in[0];
    const float* inputs = (const float*)d_in[1];
    const float* ln1_g  = (const float*)d_in[2];
    const float* ln1_b  = (const float*)d_in[3];
    const float* ln2_g  = (const float*)d_in[4];
    const float* ln2_b  = (const float*)d_in[5];
    const float* Wq     = (const float*)d_in[6];
    const float* bq     = (const float*)d_in[7];
    const float* Wk     = (const float*)d_in[8];
    const float* bk     = (const float*)d_in[9];
    const float* Wv     = (const float*)d_in[10];
    const float* bv     = (const float*)d_in[11];
    float* out = (float*)d_out;

    void *p; float *hsh, *hsl, *inh, *inl, *q, *k, *v;
    float *wqh, *wql, *wkh, *wkl, *wvh, *wvl;
    cudaGetSymbolAddress(&p, g_hsn_hi);  hsh = (float*)p;
    cudaGetSymbolAddress(&p, g_hsn_lo);  hsl = (float*)p;
    cudaGetSymbolAddress(&p, g_inpn_hi); inh = (float*)p;
    cudaGetSymbolAddress(&p, g_inpn_lo); inl = (float*)p;
    cudaGetSymbolAddress(&p, g_q);   q = (float*)p;
    cudaGetSymbolAddress(&p, g_k);   k = (float*)p;
    cudaGetSymbolAddress(&p, g_v);   v = (float*)p;
    cudaGetSymbolAddress(&p, g_wqh); wqh = (float*)p;
    cudaGetSymbolAddress(&p, g_wql); wql = (float*)p;
    cudaGetSymbolAddress(&p, g_wkh); wkh = (float*)p;
    cudaGetSymbolAddress(&p, g_wkl); wkl = (float*)p;
    cudaGetSymbolAddress(&p, g_wvh); wvh = (float*)p;
    cudaGetSymbolAddress(&p, g_wvl); wvl = (float*)p;

    // LayerNorms with split outputs
    ln_split_kernel<QDIM> <<<B_ * LQ_,  256>>>(hidden, ln1_g, ln1_b, hsh, hsl);
    ln_split_kernel<KVDIM><<<B_ * LKV_, 256>>>(inputs, ln2_g, ln2_b, inh, inl);

    // Weight splits
    split_w_kernel<<<(QDIM*CH  + 255) / 256, 256>>>(Wq, wqh, wql, QDIM*CH);
    split_w_kernel<<<(KVDIM*CH + 255) / 256, 256>>>(Wk, wkh, wkl, KVDIM*CH);
    split_w_kernel<<<(KVDIM*CH + 255) / 256, 256>>>(Wv, wvh, wvl, KVDIM*CH);

    // tf32 split GEMMs
    cudaFuncSetAttribute(gemm_tf32_kernel, cudaFuncAttributeMaxDynamicSharedMemorySize, GEMM_SMEM);
    gemm_tf32_kernel<<<dim3((B_*LQ_)/GBM,  CH/GBN), 256, GEMM_SMEM>>>(hsh, hsl, wqh, wql, bq, q, B_*LQ_,  QDIM);
    gemm_tf32_kernel<<<dim3((B_*LKV_)/GBM, CH/GBN), 256, GEMM_SMEM>>>(inh, inl, wkh, wkl, bk, k, B_*LKV_, KVDIM);
    gemm_tf32_kernel<<<dim3((B_*LKV_)/GBM, CH/GBN), 256, GEMM_SMEM>>>(inh, inl, wvh, wvl, bv, v, B_*LKV_, KVDIM);

    // tf32 mma.sync attention
    attn_mma_kernel<<<dim3(LQ_/BQ, HEADS, B_), 128>>>(q, k, v, out);
}

// round 8
// speedup vs baseline: 1.9075x; 1.9075x over previous
#include <cuda_runtime.h>
#include <math.h>
#include <stdint.h>

// ---------------- problem constants ----------------
#define B_    4
#define LQ_   512
#define LKV_  8192
#define QDIM  1024
#define KVDIM 512
#define CH    256      // QK_CH == V_CH == 256 (GEMM N)
#define HEADS 8
#define DH    32
#define QSCALE 0.2550348587f   // (1/sqrt(32)) * log2(e)

// ---------------- scratch ----------------
__device__ float g_hsn [B_*LQ_*QDIM];
__device__ float g_inpn[B_*LKV_*KVDIM];
__device__ float g_q  [B_*LQ_*CH];
__device__ float g_k  [B_*LKV_*CH];
__device__ float g_v  [B_*LKV_*CH];
__device__ float g_wq [QDIM*CH];
__device__ float g_wk [KVDIM*CH];
__device__ float g_wv [KVDIM*CH];

// ================= helpers (baseline PTX only) =================
__device__ __forceinline__ uint32_t smem_u32(const void* p){
    uint32_t a; asm("{ .reg .u64 t; cvta.to.shared.u64 t, %1; cvt.u32.u64 %0, t; }" : "=r"(a) : "l"(p)); return a;
}
__device__ __forceinline__ uint32_t f2tf32(float f){
    uint32_t t; asm("cvt.rna.tf32.f32 %0, %1;" : "=r"(t) : "f"(f)); return t;
}
__device__ __forceinline__ float fexp2(float x){
    float y; asm("ex2.approx.ftz.f32 %0, %1;" : "=f"(y) : "f"(x)); return y;
}
__device__ __forceinline__ void cpa16(uint32_t dst, const void* src){
    asm volatile("cp.async.ca.shared.global [%0], [%1], 16;" :: "r"(dst), "l"(src) : "memory");
}
#define CPA_COMMIT() asm volatile("cp.async.commit_group;" ::: "memory")
#define CPA_WAIT(n)  asm volatile("cp.async.wait_group " #n ";" ::: "memory")

// m16n8k8 tf32 mma: D = A*B + D (A row-major, B col-major)
__device__ __forceinline__ void mma8(float* c, const uint32_t* a, uint32_t b0, uint32_t b1){
    asm volatile("mma.sync.aligned.m16n8k8.row.col.f32.tf32.tf32.f32 "
        "{%0,%1,%2,%3}, {%4,%5,%6,%7}, {%8,%9}, {%0,%1,%2,%3};"
        : "+f"(c[0]), "+f"(c[1]), "+f"(c[2]), "+f"(c[3])
        : "r"(a[0]), "r"(a[1]), "r"(a[2]), "r"(a[3]), "r"(b0), "r"(b1));
}

// ---------------- LayerNorm, output RNA-rounded to tf32 ----------------
template<int N>
__global__ __launch_bounds__(256) void ln_kernel(
    const float* __restrict__ x, const float* __restrict__ g,
    const float* __restrict__ b, float* __restrict__ y)
{
    constexpr int T = 256;
    constexpr int PER = N / T;
    const int row = blockIdx.x;
    const float* xr = x + (size_t)row * N;

    float v[PER];
    float s = 0.f, sq = 0.f;
#pragma unroll
    for (int i = 0; i < PER; i++) {
        v[i] = xr[threadIdx.x + i * T];
        s  += v[i];
        sq += v[i] * v[i];
    }
#pragma unroll
    for (int o = 16; o > 0; o >>= 1) {
        s  += __shfl_xor_sync(0xffffffffu, s,  o);
        sq += __shfl_xor_sync(0xffffffffu, sq, o);
    }
    __shared__ float rs[8], rq[8];
    const int warp = threadIdx.x >> 5, lane = threadIdx.x & 31;
    if (lane == 0) { rs[warp] = s; rq[warp] = sq; }
    __syncthreads();
    if (threadIdx.x == 0) {
        float ts = 0.f, tq = 0.f;
#pragma unroll
        for (int i = 0; i < 8; i++) { ts += rs[i]; tq += rq[i]; }
        rs[0] = ts; rq[0] = tq;
    }
    __syncthreads();
    const float mean = rs[0] * (1.f / N);
    const float var  = rq[0] * (1.f / N) - mean * mean;
    const float rstd = rsqrtf(var + 1e-5f);

    float* yr = y + (size_t)row * N;
#pragma unroll
    for (int i = 0; i < PER; i++) {
        const int c = threadIdx.x + i * T;
        const float yv = (v[i] - mean) * rstd * g[c] + b[c];
        yr[c] = __uint_as_float(f2tf32(yv));   // RNA tf32: mma truncation becomes exact
    }
}

// ---------------- weight RNA-rounding (elementwise) ----------------
__global__ void round_w_kernel(const float* __restrict__ w, float* __restrict__ wr, int n)
{
    const int i = blockIdx.x * 256 + threadIdx.x;
    if (i < n) wr[i] = __uint_as_float(f2tf32(w[i]));
}

// ---------------- single-pass tf32 GEMM ----------------
// C[M,256] = A @ W + bias; A,W pre-rounded to tf32 (RNA). Output RNA-rounded.
// CTA 128x128, 8 warps (4x2), warp tile 32x64, k-step 16, cp.async x2 buffers.
#define GBM 128
#define GBN 128
#define GBK 16
#define ALD 20      // A smem leading dim (floats)
#define WLD 136     // W smem leading dim (floats)
#define ASZ (GBM*ALD)
#define WSZ (GBK*WLD)

__global__ void __launch_bounds__(256) gemm_tf32_kernel(
    const float* __restrict__ A, const float* __restrict__ W,
    const float* __restrict__ bias, float* __restrict__ C,
    int M, int K)
{
    __shared__ float sA[2][ASZ];
    __shared__ float sW[2][WSZ];

    const int tid  = threadIdx.x;
    const int wid  = tid >> 5;
    const int lane = tid & 31;
    const int g    = lane >> 2;
    const int tig  = lane & 3;
    const int bm   = blockIdx.x * GBM;
    const int bn   = blockIdx.y * GBN;
    const int wm   = (wid & 3) * 32;       // warp m offset
    const int wn   = (wid >> 2) * 64;      // warp n offset

#define G_ISSUE(s, nb) do {                                                        \
    const int _k0 = (s) * GBK;                                                     \
    _Pragma("unroll")                                                              \
    for (int i = 0; i < 2; i++) {                                                  \
        const int idx = tid + i * 256;                                             \
        const int ar = idx >> 2, aq4 = (idx & 3) * 4;                              \
        cpa16(smem_u32(&sA[nb][ar*ALD + aq4]), A + (size_t)(bm+ar)*K + _k0 + aq4); \
        const int wr = idx >> 5, wc = (idx & 31) * 4;                              \
        cpa16(smem_u32(&sW[nb][wr*WLD + wc]), W + (size_t)(_k0+wr)*CH + bn + wc);  \
    }                                                                              \
    CPA_COMMIT();                                                                  \
} while (0)

    float cacc[2][8][4];
#pragma unroll
    for (int i = 0; i < 2; i++)
#pragma unroll
        for (int n = 0; n < 8; n++)
#pragma unroll
            for (int r = 0; r < 4; r++) cacc[i][n][r] = 0.f;

    const int NS = K / GBK;
    G_ISSUE(0, 0);

    for (int s = 0; s < NS; s++) {
        const int nb = s & 1;
        if (s < NS - 1) { G_ISSUE(s + 1, (s + 1) & 1); CPA_WAIT(1); }
        else            { CPA_WAIT(0); }
        __syncthreads();

        const uint32_t* uA = (const uint32_t*)sA[nb];
        const uint32_t* uW = (const uint32_t*)sW[nb];

#pragma unroll
        for (int k8 = 0; k8 < 2; k8++) {
            const int kc = k8 * 8 + tig;
            uint32_t af[2][4];
#pragma unroll
            for (int i = 0; i < 2; i++) {
                const int r0 = (wm + i * 16 + g) * ALD;
                const int r1 = (wm + i * 16 + g + 8) * ALD;
                af[i][0] = uA[r0 + kc];     af[i][1] = uA[r1 + kc];
                af[i][2] = uA[r0 + kc + 4]; af[i][3] = uA[r1 + kc + 4];
            }
#pragma unroll
            for (int nf = 0; nf < 8; nf++) {
                const int n = wn + nf * 8 + g;
                const uint32_t b0 = uW[(k8 * 8 + tig) * WLD + n];
                const uint32_t b1 = uW[(k8 * 8 + tig + 4) * WLD + n];
                mma8(cacc[0][nf], af[0], b0, b1);
                mma8(cacc[1][nf], af[1], b0, b1);
            }
        }
        __syncthreads();
    }

    // ---- epilogue: bias, RNA-round to tf32, store ----
#pragma unroll
    for (int i = 0; i < 2; i++) {
#pragma unroll
        for (int n = 0; n < 8; n++) {
            const int col = bn + wn + n * 8 + 2 * tig;
            const float b0 = bias[col], b1 = bias[col + 1];
            const int r0 = bm + wm + i * 16 + g;
            float2 w0, w1;
            w0.x = __uint_as_float(f2tf32(cacc[i][n][0] + b0));
            w0.y = __uint_as_float(f2tf32(cacc[i][n][1] + b1));
            w1.x = __uint_as_float(f2tf32(cacc[i][n][2] + b0));
            w1.y = __uint_as_float(f2tf32(cacc[i][n][3] + b1));
            *(float2*)(C + (size_t)r0 * CH + col)       = w0;
            *(float2*)(C + (size_t)(r0 + 8) * CH + col) = w1;
        }
    }
}

// ================= mma.sync tf32 flash attention (unchanged, passing) ========
// Inputs q,k,v are already exact tf32 values -> the mma bit-truncation of
// k/v raw bits is exact (no RZ bias).
#define BQ    64
#define BKV   64
#define NT    (LKV_ / BKV)   // 128
#define LDK   36

__global__ void __launch_bounds__(128) attn_mma_kernel(
    const float* __restrict__ Q, const float* __restrict__ K,
    const float* __restrict__ V, float* __restrict__ O)
{
    __shared__ float Ks[2][BKV][LDK];
    __shared__ float Vs[2][BKV][LDK];

    const int tid  = threadIdx.x;
    const int wid  = tid >> 5;
    const int lane = tid & 31;
    const int g    = lane >> 2;
    const int tig  = lane & 3;
    const int q0   = blockIdx.x * BQ;
    const int h    = blockIdx.y;
    const int b    = blockIdx.z;
    const int qw   = q0 + wid * 16;

    const float* Qb = Q + ((size_t)(b * LQ_ + qw)) * CH + h * DH;
    const float* Kb = K + ((size_t)b * LKV_) * CH + h * DH;
    const float* Vb = V + ((size_t)b * LKV_) * CH + h * DH;

    uint32_t aq[4][4];
#pragma unroll
    for (int kc = 0; kc < 4; kc++) {
        const int c0 = kc * 8 + tig;
        aq[kc][0] = f2tf32(Qb[(size_t)g       * CH + c0    ] * QSCALE);
        aq[kc][1] = f2tf32(Qb[(size_t)(g + 8) * CH + c0    ] * QSCALE);
        aq[kc][2] = f2tf32(Qb[(size_t)g       * CH + c0 + 4] * QSCALE);
        aq[kc][3] = f2tf32(Qb[(size_t)(g + 8) * CH + c0 + 4] * QSCALE);
    }

    float oacc[4][4];
#pragma unroll
    for (int i = 0; i < 4; i++)
#pragma unroll
        for (int r = 0; r < 4; r++) oacc[i][r] = 0.f;
    float lrow[2] = {0.f, 0.f};

    const int prow = tid >> 3;
    const int pc   = (tid & 7) * 4;
#define ISSUE_TILE(j, nb) do {                                                     \
    const int _k0 = (j) * BKV;                                                     \
    _Pragma("unroll")                                                              \
    for (int t = 0; t < 4; t++) {                                                  \
        const int rw = prow + t * 16;                                              \
        cpa16(smem_u32(&Ks[nb][rw][pc]), Kb + (size_t)(_k0 + rw) * CH + pc);       \
        cpa16(smem_u32(&Vs[nb][rw][pc]), Vb + (size_t)(_k0 + rw) * CH + pc);       \
    }                                                                              \
    CPA_COMMIT();                                                                  \
} while (0)

    ISSUE_TILE(0, 0);

    for (int j = 0; j < NT; j++) {
        const int nb = j & 1;
        if (j < NT - 1) { ISSUE_TILE(j + 1, (j + 1) & 1); CPA_WAIT(1); }
        else            { CPA_WAIT(0); }
        __syncthreads();

        float sacc[8][4];
#pragma unroll
        for (int n = 0; n < 8; n++)
#pragma unroll
            for (int r = 0; r < 4; r++) sacc[n][r] = 0.f;

#pragma unroll
        for (int nch = 0; nch < 8; nch++) {
            const float* krow = &Ks[nb][nch * 8 + g][0];
#pragma unroll
            for (int kc = 0; kc < 4; kc++) {
                const uint32_t b0 = __float_as_uint(krow[kc * 8 + tig]);
                const uint32_t b1 = __float_as_uint(krow[kc * 8 + tig + 4]);
                mma8(sacc[nch], aq[kc], b0, b1);
            }
        }

#pragma unroll
        for (int n = 0; n < 8; n++) {
#pragma unroll
            for (int r = 0; r < 4; r++) {
                const float p = fexp2(sacc[n][r]);
                sacc[n][r] = p;
                lrow[r >> 1] += p;
            }
        }

#pragma unroll
        for (int kc = 0; kc < 8; kc++) {
            const int src0 = (lane & ~3) | (tig >> 1);
            const int src2 = src0 + 2;
            const float v00 = __shfl_sync(0xffffffffu, sacc[kc][0], src0);
            const float v01 = __shfl_sync(0xffffffffu, sacc[kc][1], src0);
            const float v10 = __shfl_sync(0xffffffffu, sacc[kc][2], src0);
            const float v11 = __shfl_sync(0xffffffffu, sacc[kc][3], src0);
            const float v20 = __shfl_sync(0xffffffffu, sacc[kc][0], src2);
            const float v21 = __shfl_sync(0xffffffffu, sacc[kc][1], src2);
            const float v30 = __shfl_sync(0xffffffffu, sacc[kc][2], src2);
            const float v31 = __shfl_sync(0xffffffffu, sacc[kc][3], src2);
            uint32_t ap[4];
            const bool odd = (tig & 1);
            ap[0] = f2tf32(odd ? v01 : v00);
            ap[1] = f2tf32(odd ? v11 : v10);
            ap[2] = f2tf32(odd ? v21 : v20);
            ap[3] = f2tf32(odd ? v31 : v30);

            const float* vr0 = &Vs[nb][kc * 8 + tig][0];
            const float* vr1 = &Vs[nb][kc * 8 + tig + 4][0];
#pragma unroll
            for (int nch = 0; nch < 4; nch++) {
                const uint32_t b0 = __float_as_uint(vr0[nch * 8 + g]);
                const uint32_t b1 = __float_as_uint(vr1[nch * 8 + g]);
                mma8(oacc[nch], ap, b0, b1);
            }
        }
        __syncthreads();
    }

#pragma unroll
    for (int r = 0; r < 2; r++) {
        lrow[r] += __shfl_xor_sync(0xffffffffu, lrow[r], 1);
        lrow[r] += __shfl_xor_sync(0xffffffffu, lrow[r], 2);
    }
    const float inv0 = 1.f / lrow[0];
    const float inv1 = 1.f / lrow[1];

    float* Ob = O + ((size_t)(b * LQ_ + qw)) * CH + h * DH;
#pragma unroll
    for (int nch = 0; nch < 4; nch++) {
        const int c = nch * 8 + 2 * tig;
        float2 w0 = make_float2(oacc[nch][0] * inv0, oacc[nch][1] * inv0);
        float2 w1 = make_float2(oacc[nch][2] * inv1, oacc[nch][3] * inv1);
        *(float2*)(Ob + (size_t)g       * CH + c) = w0;
        *(float2*)(Ob + (size_t)(g + 8) * CH + c) = w1;
    }
}

// ---------------- launch ----------------
extern "C" void kernel_launch(void* const* d_in, const int* in_sizes, int n_in,
                              void* d_out, int out_size)
{
    const float* hidden = (const float*)d_in[0];
    const float* inputs = (const float*)d_in[1];
    const float* ln1_g  = (const float*)d_in[2];
    const float* ln1_b  = (const float*)d_in[3];
    const float* ln2_g  = (const float*)d_in[4];
    const float* ln2_b  = (const float*)d_in[5];
    const float* Wq     = (const float*)d_in[6];
    const float* bq     = (const float*)d_in[7];
    const float* Wk     = (const float*)d_in[8];
    const float* bk     = (const float*)d_in[9];
    const float* Wv     = (const float*)d_in[10];
    const float* bv     = (const float*)d_in[11];
    float* out = (float*)d_out;

    void *p; float *hsn, *inpn, *q, *k, *v, *wq, *wk, *wv;
    cudaGetSymbolAddress(&p, g_hsn);  hsn  = (float*)p;
    cudaGetSymbolAddress(&p, g_inpn); inpn = (float*)p;
    cudaGetSymbolAddress(&p, g_q);  q  = (float*)p;
    cudaGetSymbolAddress(&p, g_k);  k  = (float*)p;
    cudaGetSymbolAddress(&p, g_v);  v  = (float*)p;
    cudaGetSymbolAddress(&p, g_wq); wq = (float*)p;
    cudaGetSymbolAddress(&p, g_wk); wk = (float*)p;
    cudaGetSymbolAddress(&p, g_wv); wv = (float*)p;

    // LayerNorms (tf32-rounded outputs)
    ln_kernel<QDIM> <<<B_ * LQ_,  256>>>(hidden, ln1_g, ln1_b, hsn);
    ln_kernel<KVDIM><<<B_ * LKV_, 256>>>(inputs, ln2_g, ln2_b, inpn);

    // Weight rounding (RNA -> unbiased tf32)
    round_w_kernel<<<(QDIM*CH  + 255) / 256, 256>>>(Wq, wq, QDIM*CH);
    round_w_kernel<<<(KVDIM*CH + 255) / 256, 256>>>(Wk, wk, KVDIM*CH);
    round_w_kernel<<<(KVDIM*CH + 255) / 256, 256>>>(Wv, wv, KVDIM*CH);

    // Single-pass tf32 GEMMs
    gemm_tf32_kernel<<<dim3((B_*LQ_)/GBM,  CH/GBN), 256>>>(hsn,  wq, bq, q, B_*LQ_,  QDIM);
    gemm_tf32_kernel<<<dim3((B_*LKV_)/GBM, CH/GBN), 256>>>(inpn, wk, bk, k, B_*LKV_, KVDIM);
    gemm_tf32_kernel<<<dim3((B_*LKV_)/GBM, CH/GBN), 256>>>(inpn, wv, bv, v, B_*LKV_, KVDIM);

    // tf32 mma.sync attention
    attn_mma_kernel<<<dim3(LQ_/BQ, HEADS, B_), 128>>>(q, k, v, out);
}

// round 9
// speedup vs baseline: 1.9831x; 1.0396x over previous
#include <cuda_runtime.h>
#include <math.h>
#include <stdint.h>

// ---------------- problem constants ----------------
#define B_    4
#define LQ_   512
#define LKV_  8192
#define QDIM  1024
#define KVDIM 512
#define CH    256      // QK_CH == V_CH == 256 (GEMM N)
#define HEADS 8
#define DH    32
#define QSCALE 0.2550348587f   // (1/sqrt(32)) * log2(e)
#define NSPLIT 2               // KV-axis split for attention

// ---------------- scratch ----------------
__device__ float g_hsn [B_*LQ_*QDIM];
__device__ float g_inpn[B_*LKV_*KVDIM];
__device__ float g_q  [B_*LQ_*CH];
__device__ float g_k  [B_*LKV_*CH];
__device__ float g_v  [B_*LKV_*CH];
__device__ float g_wq [QDIM*CH];
__device__ float g_wk [KVDIM*CH];
__device__ float g_wv [KVDIM*CH];
__device__ float g_opart[NSPLIT*B_*LQ_*CH];     // unnormalized O partials
__device__ float g_lpart[NSPLIT*B_*LQ_*HEADS];  // softmax denominators

// ================= helpers (baseline PTX only) =================
__device__ __forceinline__ uint32_t smem_u32(const void* p){
    uint32_t a; asm("{ .reg .u64 t; cvta.to.shared.u64 t, %1; cvt.u32.u64 %0, t; }" : "=r"(a) : "l"(p)); return a;
}
__device__ __forceinline__ uint32_t f2tf32(float f){
    uint32_t t; asm("cvt.rna.tf32.f32 %0, %1;" : "=r"(t) : "f"(f)); return t;
}
__device__ __forceinline__ float fexp2(float x){
    float y; asm("ex2.approx.ftz.f32 %0, %1;" : "=f"(y) : "f"(x)); return y;
}
__device__ __forceinline__ void cpa16(uint32_t dst, const void* src){
    asm volatile("cp.async.ca.shared.global [%0], [%1], 16;" :: "r"(dst), "l"(src) : "memory");
}
#define CPA_COMMIT() asm volatile("cp.async.commit_group;" ::: "memory")
#define CPA_WAIT(n)  asm volatile("cp.async.wait_group " #n ";" ::: "memory")

// m16n8k8 tf32 mma: D = A*B + D (A row-major, B col-major)
__device__ __forceinline__ void mma8(float* c, const uint32_t* a, uint32_t b0, uint32_t b1){
    asm volatile("mma.sync.aligned.m16n8k8.row.col.f32.tf32.tf32.f32 "
        "{%0,%1,%2,%3}, {%4,%5,%6,%7}, {%8,%9}, {%0,%1,%2,%3};"
        : "+f"(c[0]), "+f"(c[1]), "+f"(c[2]), "+f"(c[3])
        : "r"(a[0]), "r"(a[1]), "r"(a[2]), "r"(a[3]), "r"(b0), "r"(b1));
}

// ---------------- LayerNorm, output RNA-rounded to tf32 ----------------
template<int N>
__global__ __launch_bounds__(256) void ln_kernel(
    const float* __restrict__ x, const float* __restrict__ g,
    const float* __restrict__ b, float* __restrict__ y)
{
    constexpr int T = 256;
    constexpr int PER = N / T;
    const int row = blockIdx.x;
    const float* xr = x + (size_t)row * N;

    float v[PER];
    float s = 0.f, sq = 0.f;
#pragma unroll
    for (int i = 0; i < PER; i++) {
        v[i] = xr[threadIdx.x + i * T];
        s  += v[i];
        sq += v[i] * v[i];
    }
#pragma unroll
    for (int o = 16; o > 0; o >>= 1) {
        s  += __shfl_xor_sync(0xffffffffu, s,  o);
        sq += __shfl_xor_sync(0xffffffffu, sq, o);
    }
    __shared__ float rs[8], rq[8];
    const int warp = threadIdx.x >> 5, lane = threadIdx.x & 31;
    if (lane == 0) { rs[warp] = s; rq[warp] = sq; }
    __syncthreads();
    if (threadIdx.x == 0) {
        float ts = 0.f, tq = 0.f;
#pragma unroll
        for (int i = 0; i < 8; i++) { ts += rs[i]; tq += rq[i]; }
        rs[0] = ts; rq[0] = tq;
    }
    __syncthreads();
    const float mean = rs[0] * (1.f / N);
    const float var  = rq[0] * (1.f / N) - mean * mean;
    const float rstd = rsqrtf(var + 1e-5f);

    float* yr = y + (size_t)row * N;
#pragma unroll
    for (int i = 0; i < PER; i++) {
        const int c = threadIdx.x + i * T;
        const float yv = (v[i] - mean) * rstd * g[c] + b[c];
        yr[c] = __uint_as_float(f2tf32(yv));   // RNA tf32: mma truncation becomes exact
    }
}

// ---------------- weight RNA-rounding (elementwise) ----------------
__global__ void round_w_kernel(const float* __restrict__ w, float* __restrict__ wr, int n)
{
    const int i = blockIdx.x * 256 + threadIdx.x;
    if (i < n) wr[i] = __uint_as_float(f2tf32(w[i]));
}

// ---------------- single-pass tf32 GEMM (unchanged, near its floor) ---------
#define GBM 128
#define GBN 128
#define GBK 16
#define ALD 20      // A smem leading dim (floats)
#define WLD 136     // W smem leading dim (floats)
#define ASZ (GBM*ALD)
#define WSZ (GBK*WLD)

__global__ void __launch_bounds__(256) gemm_tf32_kernel(
    const float* __restrict__ A, const float* __restrict__ W,
    const float* __restrict__ bias, float* __restrict__ C,
    int M, int K)
{
    __shared__ float sA[2][ASZ];
    __shared__ float sW[2][WSZ];

    const int tid  = threadIdx.x;
    const int wid  = tid >> 5;
    const int lane = tid & 31;
    const int g    = lane >> 2;
    const int tig  = lane & 3;
    const int bm   = blockIdx.x * GBM;
    const int bn   = blockIdx.y * GBN;
    const int wm   = (wid & 3) * 32;
    const int wn   = (wid >> 2) * 64;

#define G_ISSUE(s, nb) do {                                                        \
    const int _k0 = (s) * GBK;                                                     \
    _Pragma("unroll")                                                              \
    for (int i = 0; i < 2; i++) {                                                  \
        const int idx = tid + i * 256;                                             \
        const int ar = idx >> 2, aq4 = (idx & 3) * 4;                              \
        cpa16(smem_u32(&sA[nb][ar*ALD + aq4]), A + (size_t)(bm+ar)*K + _k0 + aq4); \
        const int wr = idx >> 5, wc = (idx & 31) * 4;                              \
        cpa16(smem_u32(&sW[nb][wr*WLD + wc]), W + (size_t)(_k0+wr)*CH + bn + wc);  \
    }                                                                              \
    CPA_COMMIT();                                                                  \
} while (0)

    float cacc[2][8][4];
#pragma unroll
    for (int i = 0; i < 2; i++)
#pragma unroll
        for (int n = 0; n < 8; n++)
#pragma unroll
            for (int r = 0; r < 4; r++) cacc[i][n][r] = 0.f;

    const int NS = K / GBK;
    G_ISSUE(0, 0);

    for (int s = 0; s < NS; s++) {
        const int nb = s & 1;
        if (s < NS - 1) { G_ISSUE(s + 1, (s + 1) & 1); CPA_WAIT(1); }
        else            { CPA_WAIT(0); }
        __syncthreads();

        const uint32_t* uA = (const uint32_t*)sA[nb];
        const uint32_t* uW = (const uint32_t*)sW[nb];

#pragma unroll
        for (int k8 = 0; k8 < 2; k8++) {
            const int kc = k8 * 8 + tig;
            uint32_t af[2][4];
#pragma unroll
            for (int i = 0; i < 2; i++) {
                const int r0 = (wm + i * 16 + g) * ALD;
                const int r1 = (wm + i * 16 + g + 8) * ALD;
                af[i][0] = uA[r0 + kc];     af[i][1] = uA[r1 + kc];
                af[i][2] = uA[r0 + kc + 4]; af[i][3] = uA[r1 + kc + 4];
            }
#pragma unroll
            for (int nf = 0; nf < 8; nf++) {
                const int n = wn + nf * 8 + g;
                const uint32_t b0 = uW[(k8 * 8 + tig) * WLD + n];
                const uint32_t b1 = uW[(k8 * 8 + tig + 4) * WLD + n];
                mma8(cacc[0][nf], af[0], b0, b1);
                mma8(cacc[1][nf], af[1], b0, b1);
            }
        }
        __syncthreads();
    }

#pragma unroll
    for (int i = 0; i < 2; i++) {
#pragma unroll
        for (int n = 0; n < 8; n++) {
            const int col = bn + wn + n * 8 + 2 * tig;
            const float b0 = bias[col], b1 = bias[col + 1];
            const int r0 = bm + wm + i * 16 + g;
            float2 w0, w1;
            w0.x = __uint_as_float(f2tf32(cacc[i][n][0] + b0));
            w0.y = __uint_as_float(f2tf32(cacc[i][n][1] + b1));
            w1.x = __uint_as_float(f2tf32(cacc[i][n][2] + b0));
            w1.y = __uint_as_float(f2tf32(cacc[i][n][3] + b1));
            *(float2*)(C + (size_t)r0 * CH + col)       = w0;
            *(float2*)(C + (size_t)(r0 + 8) * CH + col) = w1;
        }
    }
}

// ================= split-KV mma.sync tf32 flash attention =================
// Fixed-basis softmax (p = exp2(s), basis 0) makes KV-split exactly
// associative: partials (O_unnorm, l) combine by plain addition.
// blockIdx.z = b * NSPLIT + split; each CTA does LKV/NSPLIT keys.
#define BQ    64
#define BKV   64
#define NT2   (LKV_ / NSPLIT / BKV)   // 64 tiles per CTA
#define LDK   36

__global__ void __launch_bounds__(128) attn_mma_kernel(
    const float* __restrict__ Q, const float* __restrict__ K,
    const float* __restrict__ V, float* __restrict__ Opart,
    float* __restrict__ Lpart)
{
    __shared__ float Ks[2][BKV][LDK];
    __shared__ float Vs[2][BKV][LDK];

    const int tid   = threadIdx.x;
    const int wid   = tid >> 5;
    const int lane  = tid & 31;
    const int g     = lane >> 2;
    const int tig   = lane & 3;
    const int q0    = blockIdx.x * BQ;
    const int h     = blockIdx.y;
    const int b     = blockIdx.z / NSPLIT;
    const int split = blockIdx.z % NSPLIT;
    const int qw    = q0 + wid * 16;

    const float* Qb = Q + ((size_t)(b * LQ_ + qw)) * CH + h * DH;
    const float* Kb = K + ((size_t)(b * LKV_ + split * (LKV_ / NSPLIT))) * CH + h * DH;
    const float* Vb = V + ((size_t)(b * LKV_ + split * (LKV_ / NSPLIT))) * CH + h * DH;

    uint32_t aq[4][4];
#pragma unroll
    for (int kc = 0; kc < 4; kc++) {
        const int c0 = kc * 8 + tig;
        aq[kc][0] = f2tf32(Qb[(size_t)g       * CH + c0    ] * QSCALE);
        aq[kc][1] = f2tf32(Qb[(size_t)(g + 8) * CH + c0    ] * QSCALE);
        aq[kc][2] = f2tf32(Qb[(size_t)g       * CH + c0 + 4] * QSCALE);
        aq[kc][3] = f2tf32(Qb[(size_t)(g + 8) * CH + c0 + 4] * QSCALE);
    }

    float oacc[4][4];
#pragma unroll
    for (int i = 0; i < 4; i++)
#pragma unroll
        for (int r = 0; r < 4; r++) oacc[i][r] = 0.f;
    float lrow[2] = {0.f, 0.f};

    const int prow = tid >> 3;
    const int pc   = (tid & 7) * 4;
#define ISSUE_TILE(j, nb) do {                                                     \
    const int _k0 = (j) * BKV;                                                     \
    _Pragma("unroll")                                                              \
    for (int t = 0; t < 4; t++) {                                                  \
        const int rw = prow + t * 16;                                              \
        cpa16(smem_u32(&Ks[nb][rw][pc]), Kb + (size_t)(_k0 + rw) * CH + pc);       \
        cpa16(smem_u32(&Vs[nb][rw][pc]), Vb + (size_t)(_k0 + rw) * CH + pc);       \
    }                                                                              \
    CPA_COMMIT();                                                                  \
} while (0)

    ISSUE_TILE(0, 0);

    for (int j = 0; j < NT2; j++) {
        const int nb = j & 1;
        if (j < NT2 - 1) { ISSUE_TILE(j + 1, (j + 1) & 1); CPA_WAIT(1); }
        else             { CPA_WAIT(0); }
        __syncthreads();

        float sacc[8][4];
#pragma unroll
        for (int n = 0; n < 8; n++)
#pragma unroll
            for (int r = 0; r < 4; r++) sacc[n][r] = 0.f;

#pragma unroll
        for (int nch = 0; nch < 8; nch++) {
            const float* krow = &Ks[nb][nch * 8 + g][0];
#pragma unroll
            for (int kc = 0; kc < 4; kc++) {
                const uint32_t b0 = __float_as_uint(krow[kc * 8 + tig]);
                const uint32_t b1 = __float_as_uint(krow[kc * 8 + tig + 4]);
                mma8(sacc[nch], aq[kc], b0, b1);
            }
        }

#pragma unroll
        for (int n = 0; n < 8; n++) {
#pragma unroll
            for (int r = 0; r < 4; r++) {
                const float p = fexp2(sacc[n][r]);
                sacc[n][r] = p;
                lrow[r >> 1] += p;
            }
        }

        const int src0 = (lane & ~3) | (tig >> 1);
        const int src2 = src0 + 2;
        const bool odd = (tig & 1);
#pragma unroll
        for (int kc = 0; kc < 8; kc++) {
            const float v00 = __shfl_sync(0xffffffffu, sacc[kc][0], src0);
            const float v01 = __shfl_sync(0xffffffffu, sacc[kc][1], src0);
            const float v10 = __shfl_sync(0xffffffffu, sacc[kc][2], src0);
            const float v11 = __shfl_sync(0xffffffffu, sacc[kc][3], src0);
            const float v20 = __shfl_sync(0xffffffffu, sacc[kc][0], src2);
            const float v21 = __shfl_sync(0xffffffffu, sacc[kc][1], src2);
            const float v30 = __shfl_sync(0xffffffffu, sacc[kc][2], src2);
            const float v31 = __shfl_sync(0xffffffffu, sacc[kc][3], src2);
            uint32_t ap[4];
            ap[0] = f2tf32(odd ? v01 : v00);
            ap[1] = f2tf32(odd ? v11 : v10);
            ap[2] = f2tf32(odd ? v21 : v20);
            ap[3] = f2tf32(odd ? v31 : v30);

            const float* vr0 = &Vs[nb][kc * 8 + tig][0];
            const float* vr1 = &Vs[nb][kc * 8 + tig + 4][0];
#pragma unroll
            for (int nch = 0; nch < 4; nch++) {
                const uint32_t b0 = __float_as_uint(vr0[nch * 8 + g]);
                const uint32_t b1 = __float_as_uint(vr1[nch * 8 + g]);
                mma8(oacc[nch], ap, b0, b1);
            }
        }
        __syncthreads();
    }

    // ---- reduce l across quad; write UNNORMALIZED partials ----
#pragma unroll
    for (int r = 0; r < 2; r++) {
        lrow[r] += __shfl_xor_sync(0xffffffffu, lrow[r], 1);
        lrow[r] += __shfl_xor_sync(0xffffffffu, lrow[r], 2);
    }

    float* Ob = Opart + (size_t)split * (B_ * LQ_ * CH)
              + ((size_t)(b * LQ_ + qw)) * CH + h * DH;
#pragma unroll
    for (int nch = 0; nch < 4; nch++) {
        const int c = nch * 8 + 2 * tig;
        *(float2*)(Ob + (size_t)g       * CH + c) = make_float2(oacc[nch][0], oacc[nch][1]);
        *(float2*)(Ob + (size_t)(g + 8) * CH + c) = make_float2(oacc[nch][2], oacc[nch][3]);
    }
    if (tig == 0) {
        float* Lb = Lpart + (size_t)split * (B_ * LQ_ * HEADS)
                  + ((size_t)(b * LQ_ + qw)) * HEADS + h;
        Lb[(size_t)g       * HEADS] = lrow[0];
        Lb[(size_t)(g + 8) * HEADS] = lrow[1];
    }
}

// ---------------- combine: out = (sum_s O_s) / (sum_s l_s) ----------------
__global__ void __launch_bounds__(256) combine_kernel(
    const float* __restrict__ Opart, const float* __restrict__ Lpart,
    float* __restrict__ out)
{
    const int i = blockIdx.x * 256 + threadIdx.x;   // over B*LQ*CH
    const int row = i >> 8;                          // b*LQ + q
    const int h   = (i & (CH - 1)) >> 5;
    float o = 0.f, l = 0.f;
#pragma unroll
    for (int s = 0; s < NSPLIT; s++) {
        o += Opart[(size_t)s * (B_ * LQ_ * CH) + i];
        l += Lpart[(size_t)s * (B_ * LQ_ * HEADS) + row * HEADS + h];
    }
    out[i] = o / l;
}

// ---------------- launch ----------------
extern "C" void kernel_launch(void* const* d_in, const int* in_sizes, int n_in,
                              void* d_out, int out_size)
{
    const float* hidden = (const float*)d_in[0];
    const float* inputs = (const float*)d_in[1];
    const float* ln1_g  = (const float*)d_in[2];
    const float* ln1_b  = (const float*)d_in[3];
    const float* ln2_g  = (const float*)d_in[4];
    const float* ln2_b  = (const float*)d_in[5];
    const float* Wq     = (const float*)d_in[6];
    const float* bq     = (const float*)d_in[7];
    const float* Wk     = (const float*)d_in[8];
    const float* bk     = (const float*)d_in[9];
    const float* Wv     = (const float*)d_in[10];
    const float* bv     = (const float*)d_in[11];
    float* out = (float*)d_out;

    void *p; float *hsn, *inpn, *q, *k, *v, *wq, *wk, *wv, *op, *lp;
    cudaGetSymbolAddress(&p, g_hsn);  hsn  = (float*)p;
    cudaGetSymbolAddress(&p, g_inpn); inpn = (float*)p;
    cudaGetSymbolAddress(&p, g_q);  q  = (float*)p;
    cudaGetSymbolAddress(&p, g_k);  k  = (float*)p;
    cudaGetSymbolAddress(&p, g_v);  v  = (float*)p;
    cudaGetSymbolAddress(&p, g_wq); wq = (float*)p;
    cudaGetSymbolAddress(&p, g_wk); wk = (float*)p;
    cudaGetSymbolAddress(&p, g_wv); wv = (float*)p;
    cudaGetSymbolAddress(&p, g_opart); op = (float*)p;
    cudaGetSymbolAddress(&p, g_lpart); lp = (float*)p;

    // LayerNorms (tf32-rounded outputs)
    ln_kernel<QDIM> <<<B_ * LQ_,  256>>>(hidden, ln1_g, ln1_b, hsn);
    ln_kernel<KVDIM><<<B_ * LKV_, 256>>>(inputs, ln2_g, ln2_b, inpn);

    // Weight rounding (RNA -> unbiased tf32)
    round_w_kernel<<<(QDIM*CH  + 255) / 256, 256>>>(Wq, wq, QDIM*CH);
    round_w_kernel<<<(KVDIM*CH + 255) / 256, 256>>>(Wk, wk, KVDIM*CH);
    round_w_kernel<<<(KVDIM*CH + 255) / 256, 256>>>(Wv, wv, KVDIM*CH);

    // Single-pass tf32 GEMMs
    gemm_tf32_kernel<<<dim3((B_*LQ_)/GBM,  CH/GBN), 256>>>(hsn,  wq, bq, q, B_*LQ_,  QDIM);
    gemm_tf32_kernel<<<dim3((B_*LKV_)/GBM, CH/GBN), 256>>>(inpn, wk, bk, k, B_*LKV_, KVDIM);
    gemm_tf32_kernel<<<dim3((B_*LKV_)/GBM, CH/GBN), 256>>>(inpn, wv, bv, v, B_*LKV_, KVDIM);

    // Split-KV tf32 mma.sync attention + combine
    attn_mma_kernel<<<dim3(LQ_/BQ, HEADS, B_*NSPLIT), 128>>>(q, k, v, op, lp);
    combine_kernel<<<(B_*LQ_*CH) / 256, 256>>>(op, lp, out);
}

// round 13
// speedup vs baseline: 2.2917x; 1.1556x over previous
#include <cuda_runtime.h>
#include <math.h>
#include <stdint.h>

// ---------------- problem constants ----------------
#define B_    4
#define LQ_   512
#define LKV_  8192
#define QDIM  1024
#define KVDIM 512
#define CH    256      // QK_CH == V_CH == 256 (GEMM N)
#define HEADS 8
#define DH    32
#define QSCALE 0.2550348587f   // (1/sqrt(32)) * log2(e)
#define NSPLIT 2               // KV-axis split for attention

// ---------------- scratch ----------------
__device__ float g_hsn [B_*LQ_*QDIM];
__device__ float g_inpn[B_*LKV_*KVDIM];
__device__ float g_q  [B_*LQ_*CH];
__device__ float g_k  [B_*LKV_*CH];
__device__ float g_v  [B_*LKV_*CH];
__device__ float g_wq [QDIM*CH];
__device__ float g_wk [KVDIM*CH];
__device__ float g_wv [KVDIM*CH];
__device__ float g_opart[NSPLIT*B_*LQ_*CH];     // unnormalized O partials
__device__ float g_lpart[NSPLIT*B_*LQ_*HEADS];  // softmax denominators

// ================= helpers (baseline PTX only) =================
__device__ __forceinline__ uint32_t smem_u32(const void* p){
    uint32_t a; asm("{ .reg .u64 t; cvta.to.shared.u64 t, %1; cvt.u32.u64 %0, t; }" : "=r"(a) : "l"(p)); return a;
}
__device__ __forceinline__ uint32_t f2tf32(float f){
    uint32_t t; asm("cvt.rna.tf32.f32 %0, %1;" : "=r"(t) : "f"(f)); return t;
}
__device__ __forceinline__ float fexp2(float x){
    float y; asm("ex2.approx.ftz.f32 %0, %1;" : "=f"(y) : "f"(x)); return y;
}
// pack two f32 -> bf16x2 (RNE): upper = hi, lower = lo
__device__ __forceinline__ uint32_t pack_bf16(float hi, float lo){
    uint32_t r; asm("cvt.rn.bf16x2.f32 %0, %1, %2;" : "=r"(r) : "f"(hi), "f"(lo)); return r;
}
__device__ __forceinline__ void cpa16(uint32_t dst, const void* src){
    asm volatile("cp.async.ca.shared.global [%0], [%1], 16;" :: "r"(dst), "l"(src) : "memory");
}
#define CPA_COMMIT() asm volatile("cp.async.commit_group;" ::: "memory")
#define CPA_WAIT(n)  asm volatile("cp.async.wait_group " #n ";" ::: "memory")

// m16n8k8 tf32 mma: D = A*B + D (A row-major, B col-major)
__device__ __forceinline__ void mma8(float* c, const uint32_t* a, uint32_t b0, uint32_t b1){
    asm volatile("mma.sync.aligned.m16n8k8.row.col.f32.tf32.tf32.f32 "
        "{%0,%1,%2,%3}, {%4,%5,%6,%7}, {%8,%9}, {%0,%1,%2,%3};"
        : "+f"(c[0]), "+f"(c[1]), "+f"(c[2]), "+f"(c[3])
        : "r"(a[0]), "r"(a[1]), "r"(a[2]), "r"(a[3]), "r"(b0), "r"(b1));
}
// m16n8k16 bf16 mma: D = A*B + D
__device__ __forceinline__ void mma16bf(float* c, const uint32_t* a, uint32_t b0, uint32_t b1){
    asm volatile("mma.sync.aligned.m16n8k16.row.col.f32.bf16.bf16.f32 "
        "{%0,%1,%2,%3}, {%4,%5,%6,%7}, {%8,%9}, {%0,%1,%2,%3};"
        : "+f"(c[0]), "+f"(c[1]), "+f"(c[2]), "+f"(c[3])
        : "r"(a[0]), "r"(a[1]), "r"(a[2]), "r"(a[3]), "r"(b0), "r"(b1));
}

// ---------------- LayerNorm, output RNA-rounded to tf32 ----------------
template<int N>
__global__ __launch_bounds__(256) void ln_kernel(
    const float* __restrict__ x, const float* __restrict__ g,
    const float* __restrict__ b, float* __restrict__ y)
{
    constexpr int T = 256;
    constexpr int PER = N / T;
    const int row = blockIdx.x;
    const float* xr = x + (size_t)row * N;

    float v[PER];
    float s = 0.f, sq = 0.f;
#pragma unroll
    for (int i = 0; i < PER; i++) {
        v[i] = xr[threadIdx.x + i * T];
        s  += v[i];
        sq += v[i] * v[i];
    }
#pragma unroll
    for (int o = 16; o > 0; o >>= 1) {
        s  += __shfl_xor_sync(0xffffffffu, s,  o);
        sq += __shfl_xor_sync(0xffffffffu, sq, o);
    }
    __shared__ float rs[8], rq[8];
    const int warp = threadIdx.x >> 5, lane = threadIdx.x & 31;
    if (lane == 0) { rs[warp] = s; rq[warp] = sq; }
    __syncthreads();
    if (threadIdx.x == 0) {
        float ts = 0.f, tq = 0.f;
#pragma unroll
        for (int i = 0; i < 8; i++) { ts += rs[i]; tq += rq[i]; }
        rs[0] = ts; rq[0] = tq;
    }
    __syncthreads();
    const float mean = rs[0] * (1.f / N);
    const float var  = rq[0] * (1.f / N) - mean * mean;
    const float rstd = rsqrtf(var + 1e-5f);

    float* yr = y + (size_t)row * N;
#pragma unroll
    for (int i = 0; i < PER; i++) {
        const int c = threadIdx.x + i * T;
        const float yv = (v[i] - mean) * rstd * g[c] + b[c];
        yr[c] = __uint_as_float(f2tf32(yv));   // RNA tf32: mma truncation becomes exact
    }
}

// ---------------- weight RNA-rounding (elementwise) ----------------
__global__ void round_w_kernel(const float* __restrict__ w, float* __restrict__ wr, int n)
{
    const int i = blockIdx.x * 256 + threadIdx.x;
    if (i < n) wr[i] = __uint_as_float(f2tf32(w[i]));
}

// ---------------- single-pass tf32 GEMM (unchanged, near its floor) ---------
#define GBM 128
#define GBN 128
#define GBK 16
#define ALD 20
#define WLD 136
#define ASZ (GBM*ALD)
#define WSZ (GBK*WLD)

__global__ void __launch_bounds__(256) gemm_tf32_kernel(
    const float* __restrict__ A, const float* __restrict__ W,
    const float* __restrict__ bias, float* __restrict__ C,
    int M, int K)
{
    __shared__ float sA[2][ASZ];
    __shared__ float sW[2][WSZ];

    const int tid  = threadIdx.x;
    const int wid  = tid >> 5;
    const int lane = tid & 31;
    const int g    = lane >> 2;
    const int tig  = lane & 3;
    const int bm   = blockIdx.x * GBM;
    const int bn   = blockIdx.y * GBN;
    const int wm   = (wid & 3) * 32;
    const int wn   = (wid >> 2) * 64;

#define G_ISSUE(s, nb) do {                                                        \
    const int _k0 = (s) * GBK;                                                     \
    _Pragma("unroll")                                                              \
    for (int i = 0; i < 2; i++) {                                                  \
        const int idx = tid + i * 256;                                             \
        const int ar = idx >> 2, aq4 = (idx & 3) * 4;                              \
        cpa16(smem_u32(&sA[nb][ar*ALD + aq4]), A + (size_t)(bm+ar)*K + _k0 + aq4); \
        const int wr = idx >> 5, wc = (idx & 31) * 4;                              \
        cpa16(smem_u32(&sW[nb][wr*WLD + wc]), W + (size_t)(_k0+wr)*CH + bn + wc);  \
    }                                                                              \
    CPA_COMMIT();                                                                  \
} while (0)

    float cacc[2][8][4];
#pragma unroll
    for (int i = 0; i < 2; i++)
#pragma unroll
        for (int n = 0; n < 8; n++)
#pragma unroll
            for (int r = 0; r < 4; r++) cacc[i][n][r] = 0.f;

    const int NS = K / GBK;
    G_ISSUE(0, 0);

    for (int s = 0; s < NS; s++) {
        const int nb = s & 1;
        if (s < NS - 1) { G_ISSUE(s + 1, (s + 1) & 1); CPA_WAIT(1); }
        else            { CPA_WAIT(0); }
        __syncthreads();

        const uint32_t* uA = (const uint32_t*)sA[nb];
        const uint32_t* uW = (const uint32_t*)sW[nb];

#pragma unroll
        for (int k8 = 0; k8 < 2; k8++) {
            const int kc = k8 * 8 + tig;
            uint32_t af[2][4];
#pragma unroll
            for (int i = 0; i < 2; i++) {
                const int r0 = (wm + i * 16 + g) * ALD;
                const int r1 = (wm + i * 16 + g + 8) * ALD;
                af[i][0] = uA[r0 + kc];     af[i][1] = uA[r1 + kc];
                af[i][2] = uA[r0 + kc + 4]; af[i][3] = uA[r1 + kc + 4];
            }
#pragma unroll
            for (int nf = 0; nf < 8; nf++) {
                const int n = wn + nf * 8 + g;
                const uint32_t b0 = uW[(k8 * 8 + tig) * WLD + n];
                const uint32_t b1 = uW[(k8 * 8 + tig + 4) * WLD + n];
                mma8(cacc[0][nf], af[0], b0, b1);
                mma8(cacc[1][nf], af[1], b0, b1);
            }
        }
        __syncthreads();
    }

#pragma unroll
    for (int i = 0; i < 2; i++) {
#pragma unroll
        for (int n = 0; n < 8; n++) {
            const int col = bn + wn + n * 8 + 2 * tig;
            const float b0 = bias[col], b1 = bias[col + 1];
            const int r0 = bm + wm + i * 16 + g;
            float2 w0, w1;
            w0.x = __uint_as_float(f2tf32(cacc[i][n][0] + b0));
            w0.y = __uint_as_float(f2tf32(cacc[i][n][1] + b1));
            w1.x = __uint_as_float(f2tf32(cacc[i][n][2] + b0));
            w1.y = __uint_as_float(f2tf32(cacc[i][n][3] + b1));
            *(float2*)(C + (size_t)r0 * CH + col)       = w0;
            *(float2*)(C + (size_t)(r0 + 8) * CH + col) = w1;
        }
    }
}

// ================= split-KV attention: tf32 S-phase + bf16 PV =================
// PV trick: tf32 m16n8k8 C-fragment layout == bf16 m16n8k16 A-fragment layout,
// so P packs thread-locally (cvt.rn.bf16x2) with ZERO shuffles, and k16 halves
// the PV mma count. V is transposed+converted to bf16 in smem (Vt[d][k pairs]).
// R12 bisection: end-of-loop __syncthreads RESTORED (the only sync-structure
// delta vs the known-passing R9 kernel).
#define BQ    64
#define BKV   64
#define NT2   (LKV_ / NSPLIT / BKV)   // 64 tiles per CTA
#define LDK   36
#define VTLD  36   // Vt row stride in uint32: PV reads conflict-free

__global__ void __launch_bounds__(128) attn_mma_kernel(
    const float* __restrict__ Q, const float* __restrict__ K,
    const float* __restrict__ V, float* __restrict__ Opart,
    float* __restrict__ Lpart)
{
    __shared__ float    Ks[2][BKV][LDK];
    __shared__ float    Vs[2][BKV][LDK];
    __shared__ uint32_t Vt[2][DH][VTLD];   // [d][kp]: packed bf16x2 {V[2kp+1][d], V[2kp][d]}

    const int tid   = threadIdx.x;
    const int wid   = tid >> 5;
    const int lane  = tid & 31;
    const int g     = lane >> 2;
    const int tig   = lane & 3;
    const int q0    = blockIdx.x * BQ;
    const int h     = blockIdx.y;
    const int b     = blockIdx.z / NSPLIT;
    const int split = blockIdx.z % NSPLIT;
    const int qw    = q0 + wid * 16;

    const float* Qb = Q + ((size_t)(b * LQ_ + qw)) * CH + h * DH;
    const float* Kb = K + ((size_t)(b * LKV_ + split * (LKV_ / NSPLIT))) * CH + h * DH;
    const float* Vb = V + ((size_t)(b * LKV_ + split * (LKV_ / NSPLIT))) * CH + h * DH;

    uint32_t aq[4][4];
#pragma unroll
    for (int kc = 0; kc < 4; kc++) {
        const int c0 = kc * 8 + tig;
        aq[kc][0] = f2tf32(Qb[(size_t)g       * CH + c0    ] * QSCALE);
        aq[kc][1] = f2tf32(Qb[(size_t)(g + 8) * CH + c0    ] * QSCALE);
        aq[kc][2] = f2tf32(Qb[(size_t)g       * CH + c0 + 4] * QSCALE);
        aq[kc][3] = f2tf32(Qb[(size_t)(g + 8) * CH + c0 + 4] * QSCALE);
    }

    float oacc[4][4];
#pragma unroll
    for (int i = 0; i < 4; i++)
#pragma unroll
        for (int r = 0; r < 4; r++) oacc[i][r] = 0.f;
    float lrow[2] = {0.f, 0.f};

    const int prow = tid >> 3;
    const int pc   = (tid & 7) * 4;
#define ISSUE_TILE(j, nb) do {                                                     \
    const int _k0 = (j) * BKV;                                                     \
    _Pragma("unroll")                                                              \
    for (int t = 0; t < 4; t++) {                                                  \
        const int rw = prow + t * 16;                                              \
        cpa16(smem_u32(&Ks[nb][rw][pc]), Kb + (size_t)(_k0 + rw) * CH + pc);       \
        cpa16(smem_u32(&Vs[nb][rw][pc]), Vb + (size_t)(_k0 + rw) * CH + pc);       \
    }                                                                              \
    CPA_COMMIT();                                                                  \
} while (0)

    ISSUE_TILE(0, 0);

    for (int j = 0; j < NT2; j++) {
        const int nb = j & 1;
        if (j < NT2 - 1) { ISSUE_TILE(j + 1, (j + 1) & 1); CPA_WAIT(1); }
        else             { CPA_WAIT(0); }
        __syncthreads();   // tile j (Ks,Vs) visible to all warps

        // ---- transpose+convert V: Vs[k][d] fp32 -> Vt[d][kp] packed bf16x2 ----
#pragma unroll
        for (int w = 0; w < 8; w++) {
            const int idx = tid + w * 128;          // 0..1023
            const int d   = idx & 31;
            const int kp  = idx >> 5;               // 0..31
            const float e = Vs[nb][2 * kp][d];
            const float o = Vs[nb][2 * kp + 1][d];
            Vt[nb][d][kp] = pack_bf16(o, e);
        }

        // ---- S = Q·K^T : per warp m16 x n64, K-dim 32 (tf32) ----
        float sacc[8][4];
#pragma unroll
        for (int n = 0; n < 8; n++)
#pragma unroll
            for (int r = 0; r < 4; r++) sacc[n][r] = 0.f;

#pragma unroll
        for (int nch = 0; nch < 8; nch++) {
            const float* krow = &Ks[nb][nch * 8 + g][0];
#pragma unroll
            for (int kc = 0; kc < 4; kc++) {
                const uint32_t b0 = __float_as_uint(krow[kc * 8 + tig]);
                const uint32_t b1 = __float_as_uint(krow[kc * 8 + tig + 4]);
                mma8(sacc[nch], aq[kc], b0, b1);
            }
        }

        // ---- softmax: p = exp2(s), fixed basis ----
#pragma unroll
        for (int n = 0; n < 8; n++) {
#pragma unroll
            for (int r = 0; r < 4; r++) {
                const float p = fexp2(sacc[n][r]);
                sacc[n][r] = p;
                lrow[r >> 1] += p;
            }
        }
        __syncthreads();   // Vt[nb] writes visible to all warps before PV reads

        // ---- PV (bf16 m16n8k16): A-frags = packed C-frags, no shuffles ----
#pragma unroll
        for (int kc2 = 0; kc2 < 4; kc2++) {
            uint32_t ap[4];
            ap[0] = pack_bf16(sacc[2*kc2][1],     sacc[2*kc2][0]);
            ap[1] = pack_bf16(sacc[2*kc2][3],     sacc[2*kc2][2]);
            ap[2] = pack_bf16(sacc[2*kc2+1][1],   sacc[2*kc2+1][0]);
            ap[3] = pack_bf16(sacc[2*kc2+1][3],   sacc[2*kc2+1][2]);
#pragma unroll
            for (int nch = 0; nch < 4; nch++) {
                const uint32_t* vrow = &Vt[nb][nch * 8 + g][0];
                const uint32_t b0 = vrow[8 * kc2 + tig];
                const uint32_t b1 = vrow[8 * kc2 + 4 + tig];
                mma16bf(oacc[nch], ap, b0, b1);
            }
        }
        __syncthreads();   // RESTORED (R12 bisection): all PV/Vt reads done
                           // before next iteration's cp.async overwrites
    }

    // ---- reduce l across quad; write UNNORMALIZED partials ----
#pragma unroll
    for (int r = 0; r < 2; r++) {
        lrow[r] += __shfl_xor_sync(0xffffffffu, lrow[r], 1);
        lrow[r] += __shfl_xor_sync(0xffffffffu, lrow[r], 2);
    }

    float* Ob = Opart + (size_t)split * (B_ * LQ_ * CH)
              + ((size_t)(b * LQ_ + qw)) * CH + h * DH;
#pragma unroll
    for (int nch = 0; nch < 4; nch++) {
        const int c = nch * 8 + 2 * tig;
        *(float2*)(Ob + (size_t)g       * CH + c) = make_float2(oacc[nch][0], oacc[nch][1]);
        *(float2*)(Ob + (size_t)(g + 8) * CH + c) = make_float2(oacc[nch][2], oacc[nch][3]);
    }
    if (tig == 0) {
        float* Lb = Lpart + (size_t)split * (B_ * LQ_ * HEADS)
                  + ((size_t)(b * LQ_ + qw)) * HEADS + h;
        Lb[(size_t)g       * HEADS] = lrow[0];
        Lb[(size_t)(g + 8) * HEADS] = lrow[1];
    }
}

// ---------------- combine: out = (sum_s O_s) / (sum_s l_s) ----------------
__global__ void __launch_bounds__(256) combine_kernel(
    const float* __restrict__ Opart, const float* __restrict__ Lpart,
    float* __restrict__ out)
{
    const int i = blockIdx.x * 256 + threadIdx.x;   // over B*LQ*CH
    const int row = i >> 8;                          // b*LQ + q
    const int h   = (i & (CH - 1)) >> 5;
    float o = 0.f, l = 0.f;
#pragma unroll
    for (int s = 0; s < NSPLIT; s++) {
        o += Opart[(size_t)s * (B_ * LQ_ * CH) + i];
        l += Lpart[(size_t)s * (B_ * LQ_ * HEADS) + row * HEADS + h];
    }
    out[i] = o / l;
}

// ---------------- launch ----------------
extern "C" void kernel_launch(void* const* d_in, const int* in_sizes, int n_in,
                              void* d_out, int out_size)
{
    const float* hidden = (const float*)d_in[0];
    const float* inputs = (const float*)d_in[1];
    const float* ln1_g  = (const float*)d_in[2];
    const float* ln1_b  = (const float*)d_in[3];
    const float* ln2_g  = (const float*)d_in[4];
    const float* ln2_b  = (const float*)d_in[5];
    const float* Wq     = (const float*)d_in[6];
    const float* bq     = (const float*)d_in[7];
    const float* Wk     = (const float*)d_in[8];
    const float* bk     = (const float*)d_in[9];
    const float* Wv     = (const float*)d_in[10];
    const float* bv     = (const float*)d_in[11];
    float* out = (float*)d_out;

    void *p; float *hsn, *inpn, *q, *k, *v, *wq, *wk, *wv, *op, *lp;
    cudaGetSymbolAddress(&p, g_hsn);  hsn  = (float*)p;
    cudaGetSymbolAddress(&p, g_inpn); inpn = (float*)p;
    cudaGetSymbolAddress(&p, g_q);  q  = (float*)p;
    cudaGetSymbolAddress(&p, g_k);  k  = (float*)p;
    cudaGetSymbolAddress(&p, g_v);  v  = (float*)p;
    cudaGetSymbolAddress(&p, g_wq); wq = (float*)p;
    cudaGetSymbolAddress(&p, g_wk); wk = (float*)p;
    cudaGetSymbolAddress(&p, g_wv); wv = (float*)p;
    cudaGetSymbolAddress(&p, g_opart); op = (float*)p;
    cudaGetSymbolAddress(&p, g_lpart); lp = (float*)p;

    // LayerNorms (tf32-rounded outputs)
    ln_kernel<QDIM> <<<B_ * LQ_,  256>>>(hidden, ln1_g, ln1_b, hsn);
    ln_kernel<KVDIM><<<B_ * LKV_, 256>>>(inputs, ln2_g, ln2_b, inpn);

    // Weight rounding (RNA -> unbiased tf32)
    round_w_kernel<<<(QDIM*CH  + 255) / 256, 256>>>(Wq, wq, QDIM*CH);
    round_w_kernel<<<(KVDIM*CH + 255) / 256, 256>>>(Wk, wk, KVDIM*CH);
    round_w_kernel<<<(KVDIM*CH + 255) / 256, 256>>>(Wv, wv, KVDIM*CH);

    // Single-pass tf32 GEMMs
    gemm_tf32_kernel<<<dim3((B_*LQ_)/GBM,  CH/GBN), 256>>>(hsn,  wq, bq, q, B_*LQ_,  QDIM);
    gemm_tf32_kernel<<<dim3((B_*LKV_)/GBM, CH/GBN), 256>>>(inpn, wk, bk, k, B_*LKV_, KVDIM);
    gemm_tf32_kernel<<<dim3((B_*LKV_)/GBM, CH/GBN), 256>>>(inpn, wv, bv, v, B_*LKV_, KVDIM);

    // Split-KV attention (tf32 S + bf16 PV) + combine
    attn_mma_kernel<<<dim3(LQ_/BQ, HEADS, B_*NSPLIT), 128>>>(q, k, v, op, lp);
    combine_kernel<<<(B_*LQ_*CH) / 256, 256>>>(op, lp, out);
}